// round 11
// baseline (speedup 1.0000x reference)
#include <cuda_runtime.h>
#include <cuda_fp16.h>
#include <math.h>

#define NN 100000
#define EE 3400000
#define NEG_SLOPE 0.2f

// ---------------- scratch (device globals; no allocations allowed) ----------
__device__ __half2 g_hh1[NN * 32];     // layer1 features packed (head0,head1)
__device__ float   g_as1[NN * 2];
__device__ float   g_ad1[NN * 2];
__device__ float   g_hin2[NN * 32];    // relu(mean-heads + b1)
__device__ float   g_h2[NN * 32];
__device__ float   g_as2[NN];
__device__ float   g_ad2[NN];
__device__ float   g_imp[NN];

// CSR by destination (shared by both layers)
__device__ int g_deg[NN];
__device__ int g_rowstart[NN + 1];
__device__ int g_cursor[NN];
__device__ int g_col[EE];
__device__ int g_bsum[128];            // scan phase-A partials

// top-k staging
#define TK_BLOCKS 128
__device__ float g_cand_v[TK_BLOCKS * 5];
__device__ int   g_cand_i[TK_BLOCKS * 5];

__device__ __forceinline__ float lrelu(float x) {
    return x > 0.f ? x : NEG_SLOPE * x;
}

// Inline edge-index dtype detection: int64 (values < 2^31) => all odd 32-bit
// words of the first 32 elements are zero. Warp-uniform, deterministic.
__device__ __forceinline__ int detect_idx64_warp(const int* ei32) {
    int lane = threadIdx.x & 31;
    int v = ei32[2 * lane + 1];
    unsigned nz = __ballot_sync(0xFFFFFFFFu, v != 0);
    return nz == 0 ? 1 : 0;
}

__device__ __forceinline__ int warp_incl_scan(int v, int lane) {
    #pragma unroll
    for (int o = 1; o < 32; o <<= 1) {
        int n = __shfl_up_sync(0xFFFFFFFFu, v, o);
        if (lane >= o) v += n;
    }
    return v;
}

// ------------------- K0: fat kernel = csr_count || gemm1 --------------------
__global__ void count_gemm1_kernel(const void* __restrict__ ei, int E,
                                   int egrid,
                                   const float* __restrict__ x,
                                   const float* __restrict__ W,
                                   const float* __restrict__ att_src,
                                   const float* __restrict__ att_dst,
                                   __half2* __restrict__ hh,
                                   float* __restrict__ asrc,
                                   float* __restrict__ adst,
                                   int N) {
    constexpr int IN = 64, COLS = 64, RPI = 4, ITERS = 16;
    __shared__ float Ws[IN * COLS];
    __shared__ float as_s[COLS];
    __shared__ float ad_s[COLS];
    __shared__ float xs[RPI][IN];
    __shared__ float hs[RPI][COLS];

    int t = threadIdx.x;

    if (blockIdx.x < egrid) {
        int idx64 = detect_idx64_warp((const int*)ei);
        int i = blockIdx.x * 256 + t;
        if (i >= E) return;
        int d;
        if (idx64) d = (int)((const long long*)ei)[E + i];
        else       d = ((const int*)ei)[E + i];
        atomicAdd(&g_deg[d], 1);
        return;
    }

    int gb = blockIdx.x - egrid;
    for (int i = t; i < IN * COLS; i += 256) Ws[i] = W[i];
    if (t < COLS) { as_s[t] = att_src[t]; ad_s[t] = att_dst[t]; }
    __syncthreads();

    int col  = t % COLS;
    int r    = t / COLS;
    int lane = t & 31;
    int head = col >> 5;
    long long row0 = (long long)gb * (RPI * ITERS);

    for (int it = 0; it < ITERS; ++it) {
        long long rowbase = row0 + (long long)it * RPI;
        __syncthreads();
        for (int i = t; i < RPI * IN; i += 256) {
            int rr = i / IN, k = i % IN;
            long long row = rowbase + rr;
            xs[rr][k] = (row < N) ? x[row * IN + k] : 0.f;
        }
        __syncthreads();

        long long row = rowbase + r;
        float acc = 0.f;
        #pragma unroll
        for (int k = 0; k < IN; ++k) acc += xs[r][k] * Ws[k * COLS + col];

        float s1 = acc * as_s[col];
        float s2 = acc * ad_s[col];
        #pragma unroll
        for (int o = 16; o > 0; o >>= 1) {
            s1 += __shfl_xor_sync(0xFFFFFFFFu, s1, o);
            s2 += __shfl_xor_sync(0xFFFFFFFFu, s2, o);
        }
        hs[r][col] = acc;
        if (row < N && lane == 0) {
            asrc[row * 2 + head] = s1;
            adst[row * 2 + head] = s2;
        }
        __syncthreads();
        if (col < 32 && row < N)
            hh[row * 32 + col] = __floats2half2_rn(hs[r][col], hs[r][col + 32]);
    }
}

// --------------------- 2-phase parallel exclusive scan ----------------------
// Phase A: per-block (1024 elems) sums.
__global__ void scanA_kernel(int N) {
    int tid = threadIdx.x, lane = tid & 31, wid = tid >> 5;
    int i = blockIdx.x * 1024 + tid;
    int v = (i < N) ? g_deg[i] : 0;
    #pragma unroll
    for (int o = 16; o; o >>= 1) v += __shfl_xor_sync(0xFFFFFFFFu, v, o);
    __shared__ int ws[32];
    if (lane == 0) ws[wid] = v;
    __syncthreads();
    if (wid == 0) {
        int s = ws[lane];
        #pragma unroll
        for (int o = 16; o; o >>= 1) s += __shfl_xor_sync(0xFFFFFFFFu, s, o);
        if (lane == 0) g_bsum[blockIdx.x] = s;
    }
}

// Phase C: block offset from g_bsum (inline) + local scan; writes rowstart/cursor.
__global__ void scanC_kernel(int N) {
    int tid = threadIdx.x, lane = tid & 31, wid = tid >> 5;
    __shared__ int boff_s;
    __shared__ int ws[32];

    if (wid == 0) {
        int acc = 0;
        for (int b = lane; b < blockIdx.x; b += 32) acc += g_bsum[b];
        #pragma unroll
        for (int o = 16; o; o >>= 1) acc += __shfl_xor_sync(0xFFFFFFFFu, acc, o);
        if (lane == 0) boff_s = acc;
    }

    int i = blockIdx.x * 1024 + tid;
    int v = (i < N) ? g_deg[i] : 0;
    int incl = warp_incl_scan(v, lane);
    if (lane == 31) ws[wid] = incl;
    __syncthreads();
    if (wid == 0) {
        int s = ws[lane];
        s = warp_incl_scan(s, lane);
        ws[lane] = s;
    }
    __syncthreads();
    int base = (wid > 0) ? ws[wid - 1] : 0;
    int excl = boff_s + base + incl - v;
    if (i < N) {
        g_rowstart[i] = excl;
        g_cursor[i]   = excl;
        if (i == N - 1) g_rowstart[N] = excl + v;
    }
}

// ------------------------------ CSR scatter ----------------------------------
__global__ void csr_scatter_kernel(const void* __restrict__ ei, int E) {
    int idx64 = detect_idx64_warp((const int*)ei);
    int i = blockIdx.x * blockDim.x + threadIdx.x;
    if (i >= E) return;
    int s, d;
    if (idx64) {
        const long long* p = (const long long*)ei;
        s = (int)p[i]; d = (int)p[E + i];
    } else {
        const int* p = (const int*)ei;
        s = p[i]; d = p[E + i];
    }
    int pos = atomicAdd(&g_cursor[d], 1);
    g_col[pos] = s;
}

// --------------------- layer-2 GEMM + attention coefficients ----------------
__global__ void gemm_att2_kernel(const float* __restrict__ x,
                                 const float* __restrict__ W,
                                 const float* __restrict__ att_src,
                                 const float* __restrict__ att_dst,
                                 float* __restrict__ hout,
                                 float* __restrict__ asrc,
                                 float* __restrict__ adst,
                                 int N) {
    constexpr int IN = 32, COLS = 32, RPI = 8, ITERS = 16;
    __shared__ float Ws[IN * COLS];
    __shared__ float as_s[COLS];
    __shared__ float ad_s[COLS];
    __shared__ float xs[RPI][IN];

    int t = threadIdx.x;
    for (int i = t; i < IN * COLS; i += 256) Ws[i] = W[i];
    if (t < COLS) { as_s[t] = att_src[t]; ad_s[t] = att_dst[t]; }
    __syncthreads();

    int col  = t % COLS;
    int r    = t / COLS;
    int lane = t & 31;
    long long row0 = (long long)blockIdx.x * (RPI * ITERS);

    for (int it = 0; it < ITERS; ++it) {
        long long rowbase = row0 + (long long)it * RPI;
        __syncthreads();
        for (int i = t; i < RPI * IN; i += 256) {
            int rr = i / IN, k = i % IN;
            long long row = rowbase + rr;
            xs[rr][k] = (row < N) ? x[row * IN + k] : 0.f;
        }
        __syncthreads();

        long long row = rowbase + r;
        float acc = 0.f;
        #pragma unroll
        for (int k = 0; k < IN; ++k) acc += xs[r][k] * Ws[k * COLS + col];

        float s1 = acc * as_s[col];
        float s2 = acc * ad_s[col];
        #pragma unroll
        for (int o = 16; o > 0; o >>= 1) {
            s1 += __shfl_xor_sync(0xFFFFFFFFu, s1, o);
            s2 += __shfl_xor_sync(0xFFFFFFFFu, s2, o);
        }
        if (row < N) {
            hout[row * COLS + col] = acc;
            if (lane == 0) {
                asrc[row] = s1;
                adst[row] = s2;
            }
        }
    }
}

// --------- layer-1 softmax aggregation: warp per dst, half2 features --------
// smem holds (idx, w0, w1) packed per edge -> one LDS.128 per edge in the
// gather loop; 32-bit index arithmetic throughout.
__global__ void gat_agg1_kernel(const float* __restrict__ asrc,
                                const float* __restrict__ adst,
                                const __half2* __restrict__ hh,
                                const float* __restrict__ bias,
                                float* __restrict__ outv,
                                int N) {
    __shared__ float4 s_pk[8][32];

    int warp_id = (blockIdx.x * blockDim.x + threadIdx.x) >> 5;
    int lane  = threadIdx.x & 31;
    int wslot = (threadIdx.x >> 5) & 7;
    if (warp_id >= N) return;
    int d = warp_id;

    float ad0 = adst[d * 2 + 0];
    float ad1 = adst[d * 2 + 1];
    float w_self0 = __expf(lrelu(asrc[d * 2 + 0] + ad0));
    float w_self1 = __expf(lrelu(asrc[d * 2 + 1] + ad1));
    float2 hself = __half22float2(hh[d * 32 + lane]);
    float den0 = (lane == 0) ? w_self0 : 0.f;
    float den1 = (lane == 0) ? w_self1 : 0.f;
    float acc0 = w_self0 * hself.x;
    float acc1 = w_self1 * hself.y;

    int beg = g_rowstart[d], end = g_rowstart[d + 1];
    for (int base = beg; base < end; base += 32) {
        int j = base + lane;
        bool valid = j < end;
        int s = valid ? g_col[j] : 0;

        float2 a2 = valid ? ((const float2*)asrc)[s] : make_float2(0.f, 0.f);
        float w0 = valid ? __expf(lrelu(a2.x + ad0)) : 0.f;
        float w1 = valid ? __expf(lrelu(a2.y + ad1)) : 0.f;
        den0 += w0; den1 += w1;
        s_pk[wslot][lane] = make_float4(__int_as_float(s), w0, w1, 0.f);
        __syncwarp();

        int cnt = end - base; if (cnt > 32) cnt = 32;
        if (cnt == 32) {
            #pragma unroll 8
            for (int k = 0; k < 32; ++k) {
                float4 p = s_pk[wslot][k];
                int sk = __float_as_int(p.x);
                float2 f = __half22float2(hh[sk * 32 + lane]);
                acc0 += p.y * f.x;
                acc1 += p.z * f.y;
            }
        } else {
            for (int k = 0; k < cnt; ++k) {
                float4 p = s_pk[wslot][k];
                int sk = __float_as_int(p.x);
                float2 f = __half22float2(hh[sk * 32 + lane]);
                acc0 += p.y * f.x;
                acc1 += p.z * f.y;
            }
        }
        __syncwarp();
    }

    #pragma unroll
    for (int o = 16; o; o >>= 1) {
        den0 += __shfl_xor_sync(0xFFFFFFFFu, den0, o);
        den1 += __shfl_xor_sync(0xFFFFFFFFu, den1, o);
    }
    float v = 0.5f * (acc0 / (den0 + 1e-16f) + acc1 / (den1 + 1e-16f)) + bias[lane];
    outv[d * 32 + lane] = fmaxf(v, 0.f);
}

// --------- layer-2 softmax aggregation: warp per dst, fp32 features ---------
// smem holds (idx, w) packed -> one LDS.64 per edge; 32-bit index math.
__global__ void gat_agg2_kernel(const float* __restrict__ asrc,
                                const float* __restrict__ adst,
                                const float* __restrict__ hfeat,
                                const float* __restrict__ bias,
                                float* __restrict__ outv,
                                float* __restrict__ imp_a,
                                float* __restrict__ imp_b,   // may be null
                                int N) {
    __shared__ float2 s_pk[8][32];

    int warp_id = (blockIdx.x * blockDim.x + threadIdx.x) >> 5;
    int lane  = threadIdx.x & 31;
    int wslot = (threadIdx.x >> 5) & 7;
    if (warp_id >= N) return;
    int d = warp_id;

    float ad0 = adst[d];
    float w_self = __expf(lrelu(asrc[d] + ad0));
    float den = (lane == 0) ? w_self : 0.f;
    float acc = w_self * hfeat[d * 32 + lane];

    int beg = g_rowstart[d], end = g_rowstart[d + 1];
    for (int base = beg; base < end; base += 32) {
        int j = base + lane;
        bool valid = j < end;
        int s = valid ? g_col[j] : 0;

        float w = valid ? __expf(lrelu(asrc[s] + ad0)) : 0.f;
        den += w;
        s_pk[wslot][lane] = make_float2(__int_as_float(s), w);
        __syncwarp();

        int cnt = end - base; if (cnt > 32) cnt = 32;
        if (cnt == 32) {
            #pragma unroll 8
            for (int k = 0; k < 32; ++k) {
                float2 p = s_pk[wslot][k];
                int sk = __float_as_int(p.x);
                acc += p.y * hfeat[sk * 32 + lane];
            }
        } else {
            for (int k = 0; k < cnt; ++k) {
                float2 p = s_pk[wslot][k];
                int sk = __float_as_int(p.x);
                acc += p.y * hfeat[sk * 32 + lane];
            }
        }
        __syncwarp();
    }

    #pragma unroll
    for (int o = 16; o; o >>= 1)
        den += __shfl_xor_sync(0xFFFFFFFFu, den, o);
    float v = acc / (den + 1e-16f) + bias[lane];
    outv[d * 32 + lane] = v;
    float ss = v * v;
    #pragma unroll
    for (int o = 16; o; o >>= 1)
        ss += __shfl_xor_sync(0xFFFFFFFFu, ss, o);
    if (lane == 0) {
        float nm = sqrtf(ss);
        imp_a[d] = nm;
        if (imp_b) imp_b[d] = nm;
    }
}

// --------------------------------- top-k ------------------------------------
__global__ void topk_stage1_kernel(const float* __restrict__ imp, int N) {
    __shared__ float bv[256];
    __shared__ int   bi[256];
    __shared__ int   chosen[5];
    int chunk = (N + TK_BLOCKS - 1) / TK_BLOCKS;
    int lo = blockIdx.x * chunk;
    int hi = lo + chunk; if (hi > N) hi = N;
    for (int r = 0; r < 5; ++r) {
        float best = -1e30f; int besti = 0x7FFFFFFF;
        for (int i = lo + threadIdx.x; i < hi; i += 256) {
            bool skip = false;
            for (int c = 0; c < r; ++c) if (chosen[c] == i) skip = true;
            if (skip) continue;
            float v = imp[i];
            if (v > best || (v == best && i < besti)) { best = v; besti = i; }
        }
        bv[threadIdx.x] = best;
        bi[threadIdx.x] = besti;
        __syncthreads();
        if (threadIdx.x == 0) {
            float B = -1e30f; int BI = 0x7FFFFFFF;
            for (int t = 0; t < 256; ++t)
                if (bv[t] > B || (bv[t] == B && bi[t] < BI)) { B = bv[t]; BI = bi[t]; }
            chosen[r] = BI;
            g_cand_v[blockIdx.x * 5 + r] = B;
            g_cand_i[blockIdx.x * 5 + r] = BI;
        }
        __syncthreads();
    }
}

__global__ void topk_stage2_kernel(float* __restrict__ out_idx) {
    __shared__ float bv[256];
    __shared__ int   bi[256];
    __shared__ int   chosen[5];
    const int M = TK_BLOCKS * 5;
    for (int r = 0; r < 5; ++r) {
        float best = -1e30f; int besti = 0x7FFFFFFF;
        for (int i = threadIdx.x; i < M; i += 256) {
            int gi = g_cand_i[i];
            bool skip = false;
            for (int c = 0; c < r; ++c) if (chosen[c] == gi) skip = true;
            if (skip) continue;
            float v = g_cand_v[i];
            if (v > best || (v == best && gi < besti)) { best = v; besti = gi; }
        }
        bv[threadIdx.x] = best;
        bi[threadIdx.x] = besti;
        __syncthreads();
        if (threadIdx.x == 0) {
            float B = -1e30f; int BI = 0x7FFFFFFF;
            for (int t = 0; t < 256; ++t)
                if (bv[t] > B || (bv[t] == B && bi[t] < BI)) { B = bv[t]; BI = bi[t]; }
            chosen[r] = BI;
            if (out_idx) out_idx[r] = (float)BI;
        }
        __syncthreads();
    }
}

// --------------------------------- launch -----------------------------------
extern "C" void kernel_launch(void* const* d_in, const int* in_sizes, int n_in,
                              void* d_out, int out_size) {
    const float* x    = (const float*)d_in[0];
    const void*  ei   = d_in[1];
    const float* W1   = (const float*)d_in[2];
    const float* as1w = (const float*)d_in[3];
    const float* ad1w = (const float*)d_in[4];
    const float* b1   = (const float*)d_in[5];
    const float* W2   = (const float*)d_in[6];
    const float* as2w = (const float*)d_in[7];
    const float* ad2w = (const float*)d_in[8];
    const float* b2   = (const float*)d_in[9];
    float* out = (float*)d_out;

    int N = in_sizes[0] / 64;
    int E = in_sizes[1] / 2;
    if (N > NN) N = NN;
    if (E > EE) E = EE;

    float *p_as1, *p_ad1, *p_hin2, *p_h2, *p_as2, *p_ad2, *p_imp;
    __half2 *p_hh1;
    int *p_deg;
    cudaGetSymbolAddress((void**)&p_hh1,  g_hh1);
    cudaGetSymbolAddress((void**)&p_as1,  g_as1);
    cudaGetSymbolAddress((void**)&p_ad1,  g_ad1);
    cudaGetSymbolAddress((void**)&p_hin2, g_hin2);
    cudaGetSymbolAddress((void**)&p_h2,   g_h2);
    cudaGetSymbolAddress((void**)&p_as2,  g_as2);
    cudaGetSymbolAddress((void**)&p_ad2,  g_ad2);
    cudaGetSymbolAddress((void**)&p_imp,  g_imp);
    cudaGetSymbolAddress((void**)&p_deg,  g_deg);

    cudaMemsetAsync(p_deg, 0, (size_t)N * sizeof(int));

    int egrid  = (E + 255) / 256;
    int g1grid = (N + 63) / 64;
    int NB     = (N + 1023) / 1024;   // <= 98

    // K0: csr_count || gemm1(+pack)
    count_gemm1_kernel<<<egrid + g1grid, 256>>>(ei, E, egrid, x, W1, as1w,
                                                ad1w, p_hh1, p_as1, p_ad1, N);
    // 2-phase parallel scan (scanC computes its own block offsets)
    scanA_kernel<<<NB, 1024>>>(N);
    scanC_kernel<<<NB, 1024>>>(N);

    csr_scatter_kernel<<<egrid, 256>>>(ei, E);

    // layer-1 aggregation
    gat_agg1_kernel<<<(N + 7) / 8, 256>>>(p_as1, p_ad1, p_hh1, b1, p_hin2, N);

    // layer-2 GEMM
    gemm_att2_kernel<<<(N + 127) / 128, 256>>>(p_hin2, W2, as2w, ad2w,
                                               p_h2, p_as2, p_ad2, N);

    float* embeds_dst = (out_size >= N * 32) ? out : p_h2;
    float* imp_dst    = (out_size >= N * 33) ? (out + (size_t)N * 32) : nullptr;
    float* idx_dst    = (out_size >= N * 33 + 5) ? (out + (size_t)N * 33) : nullptr;

    // layer-2 aggregation
    gat_agg2_kernel<<<(N + 7) / 8, 256>>>(p_as2, p_ad2, p_h2, b2,
                                          embeds_dst, p_imp, imp_dst, N);

    // top-k (two-stage)
    topk_stage1_kernel<<<TK_BLOCKS, 256>>>(p_imp, N);
    topk_stage2_kernel<<<1, 256>>>(idx_dst);
}

// round 12
// speedup vs baseline: 1.1175x; 1.1175x over previous
#include <cuda_runtime.h>
#include <cuda_fp16.h>
#include <math.h>

#define NN 100000
#define EE 3400000
#define NEG_SLOPE 0.2f

// ---------------- scratch (device globals; no allocations allowed) ----------
__device__ __half2 g_hh1[NN * 32];     // layer1 features packed (head0,head1)
__device__ float   g_as1[NN * 2];
__device__ float   g_ad1[NN * 2];
__device__ float   g_h2[NN * 32];
__device__ float   g_as2[NN];
__device__ float   g_ad2[NN];
__device__ float   g_imp[NN];

// CSR by destination (shared by both layers)
__device__ int g_deg[NN];              // zero-init at load; re-zeroed by scatter
__device__ int g_rowstart[NN + 1];
__device__ int g_cursor[NN];
__device__ int g_col[EE];
__device__ int g_bsum[128];            // scan phase-A partials

// top-k staging
#define TK_BLOCKS 128
__device__ float g_cand_v[TK_BLOCKS * 5];
__device__ int   g_cand_i[TK_BLOCKS * 5];

__device__ __forceinline__ float lrelu(float x) {
    return x > 0.f ? x : NEG_SLOPE * x;
}

// Inline edge-index dtype detection: int64 (values < 2^31) => all odd 32-bit
// words of the first 32 elements are zero. Warp-uniform, deterministic.
__device__ __forceinline__ int detect_idx64_warp(const int* ei32) {
    int lane = threadIdx.x & 31;
    int v = ei32[2 * lane + 1];
    unsigned nz = __ballot_sync(0xFFFFFFFFu, v != 0);
    return nz == 0 ? 1 : 0;
}

__device__ __forceinline__ int warp_incl_scan(int v, int lane) {
    #pragma unroll
    for (int o = 1; o < 32; o <<= 1) {
        int n = __shfl_up_sync(0xFFFFFFFFu, v, o);
        if (lane >= o) v += n;
    }
    return v;
}

// ------------------- K0: fat kernel = csr_count || gemm1 --------------------
__global__ void count_gemm1_kernel(const void* __restrict__ ei, int E,
                                   int egrid,
                                   const float* __restrict__ x,
                                   const float* __restrict__ W,
                                   const float* __restrict__ att_src,
                                   const float* __restrict__ att_dst,
                                   __half2* __restrict__ hh,
                                   float* __restrict__ asrc,
                                   float* __restrict__ adst,
                                   int N) {
    constexpr int IN = 64, COLS = 64, RPI = 4, ITERS = 16;
    __shared__ float Ws[IN * COLS];
    __shared__ float as_s[COLS];
    __shared__ float ad_s[COLS];
    __shared__ float xs[RPI][IN];
    __shared__ float hs[RPI][COLS];

    int t = threadIdx.x;

    if (blockIdx.x < egrid) {
        int idx64 = detect_idx64_warp((const int*)ei);
        int i = blockIdx.x * 256 + t;
        if (i >= E) return;
        int d;
        if (idx64) d = (int)((const long long*)ei)[E + i];
        else       d = ((const int*)ei)[E + i];
        atomicAdd(&g_deg[d], 1);
        return;
    }

    int gb = blockIdx.x - egrid;
    for (int i = t; i < IN * COLS; i += 256) Ws[i] = W[i];
    if (t < COLS) { as_s[t] = att_src[t]; ad_s[t] = att_dst[t]; }
    __syncthreads();

    int col  = t % COLS;
    int r    = t / COLS;
    int lane = t & 31;
    int head = col >> 5;
    long long row0 = (long long)gb * (RPI * ITERS);

    for (int it = 0; it < ITERS; ++it) {
        long long rowbase = row0 + (long long)it * RPI;
        __syncthreads();
        for (int i = t; i < RPI * IN; i += 256) {
            int rr = i / IN, k = i % IN;
            long long row = rowbase + rr;
            xs[rr][k] = (row < N) ? x[row * IN + k] : 0.f;
        }
        __syncthreads();

        long long row = rowbase + r;
        float acc = 0.f;
        #pragma unroll
        for (int k = 0; k < IN; ++k) acc += xs[r][k] * Ws[k * COLS + col];

        float s1 = acc * as_s[col];
        float s2 = acc * ad_s[col];
        #pragma unroll
        for (int o = 16; o > 0; o >>= 1) {
            s1 += __shfl_xor_sync(0xFFFFFFFFu, s1, o);
            s2 += __shfl_xor_sync(0xFFFFFFFFu, s2, o);
        }
        hs[r][col] = acc;
        if (row < N && lane == 0) {
            asrc[row * 2 + head] = s1;
            adst[row * 2 + head] = s2;
        }
        __syncthreads();
        if (col < 32 && row < N)
            hh[row * 32 + col] = __floats2half2_rn(hs[r][col], hs[r][col + 32]);
    }
}

// --------------------- 2-phase parallel exclusive scan ----------------------
__global__ void scanA_kernel(int N) {
    int tid = threadIdx.x, lane = tid & 31, wid = tid >> 5;
    int i = blockIdx.x * 1024 + tid;
    int v = (i < N) ? g_deg[i] : 0;
    #pragma unroll
    for (int o = 16; o; o >>= 1) v += __shfl_xor_sync(0xFFFFFFFFu, v, o);
    __shared__ int ws[32];
    if (lane == 0) ws[wid] = v;
    __syncthreads();
    if (wid == 0) {
        int s = ws[lane];
        #pragma unroll
        for (int o = 16; o; o >>= 1) s += __shfl_xor_sync(0xFFFFFFFFu, s, o);
        if (lane == 0) g_bsum[blockIdx.x] = s;
    }
}

__global__ void scanC_kernel(int N) {
    int tid = threadIdx.x, lane = tid & 31, wid = tid >> 5;
    __shared__ int boff_s;
    __shared__ int ws[32];

    if (wid == 0) {
        int acc = 0;
        for (int b = lane; b < blockIdx.x; b += 32) acc += g_bsum[b];
        #pragma unroll
        for (int o = 16; o; o >>= 1) acc += __shfl_xor_sync(0xFFFFFFFFu, acc, o);
        if (lane == 0) boff_s = acc;
    }

    int i = blockIdx.x * 1024 + tid;
    int v = (i < N) ? g_deg[i] : 0;
    int incl = warp_incl_scan(v, lane);
    if (lane == 31) ws[wid] = incl;
    __syncthreads();
    if (wid == 0) {
        int s = ws[lane];
        s = warp_incl_scan(s, lane);
        ws[lane] = s;
    }
    __syncthreads();
    int base = (wid > 0) ? ws[wid - 1] : 0;
    int excl = boff_s + base + incl - v;
    if (i < N) {
        g_rowstart[i] = excl;
        g_cursor[i]   = excl;
        if (i == N - 1) g_rowstart[N] = excl + v;
    }
}

// --------------- CSR scatter (also re-zeroes g_deg for next call) -----------
__global__ void csr_scatter_kernel(const void* __restrict__ ei, int E, int N) {
    int idx64 = detect_idx64_warp((const int*)ei);
    int i = blockIdx.x * blockDim.x + threadIdx.x;
    if (i < N) g_deg[i] = 0;          // restore zero-invariant for next launch
    if (i >= E) return;
    int s, d;
    if (idx64) {
        const long long* p = (const long long*)ei;
        s = (int)p[i]; d = (int)p[E + i];
    } else {
        const int* p = (const int*)ei;
        s = p[i]; d = p[E + i];
    }
    int pos = atomicAdd(&g_cursor[d], 1);
    g_col[pos] = s;
}

// ----- layer-1 aggregation FUSED with layer-2 GEMM + attention coefs --------
// warp per dst node; lane = feature dim. After computing hin2 row, multiply
// by W2 (shared) in-place and emit h2 row + as2/ad2 scalars.
__global__ void gat_agg1_fused_kernel(const float* __restrict__ asrc,
                                      const float* __restrict__ adst,
                                      const __half2* __restrict__ hh,
                                      const float* __restrict__ b1,
                                      const float* __restrict__ W2,
                                      const float* __restrict__ as2w,
                                      const float* __restrict__ ad2w,
                                      float* __restrict__ h2out,
                                      float* __restrict__ as2,
                                      float* __restrict__ ad2,
                                      int N) {
    __shared__ int   s_idx[8][32];
    __shared__ float s_w[8][2][32];
    __shared__ float W2s[32 * 32];
    __shared__ float a2s_s[32], a2d_s[32];

    int t = threadIdx.x;
    for (int i = t; i < 1024; i += 256) W2s[i] = W2[i];
    if (t < 32) { a2s_s[t] = as2w[t]; a2d_s[t] = ad2w[t]; }
    __syncthreads();

    int warp_id = (blockIdx.x * blockDim.x + t) >> 5;
    int lane  = t & 31;
    int wslot = (t >> 5) & 7;
    if (warp_id >= N) return;
    int d = warp_id;

    float ad0 = adst[d * 2 + 0];
    float ad1 = adst[d * 2 + 1];
    float w_self0 = __expf(lrelu(asrc[d * 2 + 0] + ad0));
    float w_self1 = __expf(lrelu(asrc[d * 2 + 1] + ad1));
    float2 hself = __half22float2(hh[d * 32 + lane]);
    float den0 = (lane == 0) ? w_self0 : 0.f;
    float den1 = (lane == 0) ? w_self1 : 0.f;
    float acc0 = w_self0 * hself.x;
    float acc1 = w_self1 * hself.y;

    int beg = g_rowstart[d], end = g_rowstart[d + 1];
    for (int base = beg; base < end; base += 32) {
        int j = base + lane;
        bool valid = j < end;
        int s = valid ? g_col[j] : 0;
        s_idx[wslot][lane] = s;

        float2 a2 = valid ? ((const float2*)asrc)[s] : make_float2(0.f, 0.f);
        float w0 = valid ? __expf(lrelu(a2.x + ad0)) : 0.f;
        float w1 = valid ? __expf(lrelu(a2.y + ad1)) : 0.f;
        den0 += w0; den1 += w1;
        s_w[wslot][0][lane] = w0;
        s_w[wslot][1][lane] = w1;
        __syncwarp();

        int cnt = end - base; if (cnt > 32) cnt = 32;
        if (cnt == 32) {
            #pragma unroll 8
            for (int k = 0; k < 32; ++k) {
                int sk = s_idx[wslot][k];
                float2 f = __half22float2(hh[sk * 32 + lane]);
                acc0 += s_w[wslot][0][k] * f.x;
                acc1 += s_w[wslot][1][k] * f.y;
            }
        } else {
            for (int k = 0; k < cnt; ++k) {
                int sk = s_idx[wslot][k];
                float2 f = __half22float2(hh[sk * 32 + lane]);
                acc0 += s_w[wslot][0][k] * f.x;
                acc1 += s_w[wslot][1][k] * f.y;
            }
        }
        __syncwarp();
    }

    #pragma unroll
    for (int o = 16; o; o >>= 1) {
        den0 += __shfl_xor_sync(0xFFFFFFFFu, den0, o);
        den1 += __shfl_xor_sync(0xFFFFFFFFu, den1, o);
    }
    float v = 0.5f * (acc0 / (den0 + 1e-16f) + acc1 / (den1 + 1e-16f)) + b1[lane];
    v = fmaxf(v, 0.f);                 // hin2 value for (d, lane)

    // ---- fused layer-2 GEMM (32x32) + attention coefficients ----
    s_w[wslot][0][lane] = v;
    __syncwarp();
    float h2v = 0.f;
    #pragma unroll
    for (int k = 0; k < 32; ++k)
        h2v += s_w[wslot][0][k] * W2s[k * 32 + lane];
    h2out[d * 32 + lane] = h2v;
    float c1 = h2v * a2s_s[lane];
    float c2 = h2v * a2d_s[lane];
    #pragma unroll
    for (int o = 16; o; o >>= 1) {
        c1 += __shfl_xor_sync(0xFFFFFFFFu, c1, o);
        c2 += __shfl_xor_sync(0xFFFFFFFFu, c2, o);
    }
    if (lane == 0) { as2[d] = c1; ad2[d] = c2; }
}

// --------- layer-2 softmax aggregation: warp per dst, fp32 features ---------
__global__ void gat_agg2_kernel(const float* __restrict__ asrc,
                                const float* __restrict__ adst,
                                const float* __restrict__ hfeat,
                                const float* __restrict__ bias,
                                float* __restrict__ outv,
                                float* __restrict__ imp_a,
                                float* __restrict__ imp_b,   // may be null
                                int N) {
    __shared__ int   s_idx[8][32];
    __shared__ float s_w[8][32];

    int warp_id = (blockIdx.x * blockDim.x + threadIdx.x) >> 5;
    int lane  = threadIdx.x & 31;
    int wslot = (threadIdx.x >> 5) & 7;
    if (warp_id >= N) return;
    int d = warp_id;

    float ad0 = adst[d];
    float w_self = __expf(lrelu(asrc[d] + ad0));
    float den = (lane == 0) ? w_self : 0.f;
    float acc = w_self * hfeat[d * 32 + lane];

    int beg = g_rowstart[d], end = g_rowstart[d + 1];
    for (int base = beg; base < end; base += 32) {
        int j = base + lane;
        bool valid = j < end;
        int s = valid ? g_col[j] : 0;
        s_idx[wslot][lane] = s;

        float w = valid ? __expf(lrelu(asrc[s] + ad0)) : 0.f;
        den += w;
        s_w[wslot][lane] = w;
        __syncwarp();

        int cnt = end - base; if (cnt > 32) cnt = 32;
        if (cnt == 32) {
            #pragma unroll 8
            for (int k = 0; k < 32; ++k) {
                int sk = s_idx[wslot][k];
                acc += s_w[wslot][k] * hfeat[sk * 32 + lane];
            }
        } else {
            for (int k = 0; k < cnt; ++k) {
                int sk = s_idx[wslot][k];
                acc += s_w[wslot][k] * hfeat[sk * 32 + lane];
            }
        }
        __syncwarp();
    }

    #pragma unroll
    for (int o = 16; o; o >>= 1)
        den += __shfl_xor_sync(0xFFFFFFFFu, den, o);
    float v = acc / (den + 1e-16f) + bias[lane];
    outv[d * 32 + lane] = v;
    float ss = v * v;
    #pragma unroll
    for (int o = 16; o; o >>= 1)
        ss += __shfl_xor_sync(0xFFFFFFFFu, ss, o);
    if (lane == 0) {
        float nm = sqrtf(ss);
        imp_a[d] = nm;
        if (imp_b) imp_b[d] = nm;
    }
}

// --------------------------------- top-k ------------------------------------
__global__ void topk_stage1_kernel(const float* __restrict__ imp, int N) {
    __shared__ float bv[256];
    __shared__ int   bi[256];
    __shared__ int   chosen[5];
    int chunk = (N + TK_BLOCKS - 1) / TK_BLOCKS;
    int lo = blockIdx.x * chunk;
    int hi = lo + chunk; if (hi > N) hi = N;
    for (int r = 0; r < 5; ++r) {
        float best = -1e30f; int besti = 0x7FFFFFFF;
        for (int i = lo + threadIdx.x; i < hi; i += 256) {
            bool skip = false;
            for (int c = 0; c < r; ++c) if (chosen[c] == i) skip = true;
            if (skip) continue;
            float v = imp[i];
            if (v > best || (v == best && i < besti)) { best = v; besti = i; }
        }
        bv[threadIdx.x] = best;
        bi[threadIdx.x] = besti;
        __syncthreads();
        if (threadIdx.x == 0) {
            float B = -1e30f; int BI = 0x7FFFFFFF;
            for (int t = 0; t < 256; ++t)
                if (bv[t] > B || (bv[t] == B && bi[t] < BI)) { B = bv[t]; BI = bi[t]; }
            chosen[r] = BI;
            g_cand_v[blockIdx.x * 5 + r] = B;
            g_cand_i[blockIdx.x * 5 + r] = BI;
        }
        __syncthreads();
    }
}

__global__ void topk_stage2_kernel(float* __restrict__ out_idx) {
    __shared__ float bv[256];
    __shared__ int   bi[256];
    __shared__ int   chosen[5];
    const int M = TK_BLOCKS * 5;
    for (int r = 0; r < 5; ++r) {
        float best = -1e30f; int besti = 0x7FFFFFFF;
        for (int i = threadIdx.x; i < M; i += 256) {
            int gi = g_cand_i[i];
            bool skip = false;
            for (int c = 0; c < r; ++c) if (chosen[c] == gi) skip = true;
            if (skip) continue;
            float v = g_cand_v[i];
            if (v > best || (v == best && gi < besti)) { best = v; besti = gi; }
        }
        bv[threadIdx.x] = best;
        bi[threadIdx.x] = besti;
        __syncthreads();
        if (threadIdx.x == 0) {
            float B = -1e30f; int BI = 0x7FFFFFFF;
            for (int t = 0; t < 256; ++t)
                if (bv[t] > B || (bv[t] == B && bi[t] < BI)) { B = bv[t]; BI = bi[t]; }
            chosen[r] = BI;
            if (out_idx) out_idx[r] = (float)BI;
        }
        __syncthreads();
    }
}

// --------------------------------- launch -----------------------------------
extern "C" void kernel_launch(void* const* d_in, const int* in_sizes, int n_in,
                              void* d_out, int out_size) {
    const float* x    = (const float*)d_in[0];
    const void*  ei   = d_in[1];
    const float* W1   = (const float*)d_in[2];
    const float* as1w = (const float*)d_in[3];
    const float* ad1w = (const float*)d_in[4];
    const float* b1   = (const float*)d_in[5];
    const float* W2   = (const float*)d_in[6];
    const float* as2w = (const float*)d_in[7];
    const float* ad2w = (const float*)d_in[8];
    const float* b2   = (const float*)d_in[9];
    float* out = (float*)d_out;

    int N = in_sizes[0] / 64;
    int E = in_sizes[1] / 2;
    if (N > NN) N = NN;
    if (E > EE) E = EE;

    float *p_as1, *p_ad1, *p_h2, *p_as2, *p_ad2, *p_imp;
    __half2 *p_hh1;
    cudaGetSymbolAddress((void**)&p_hh1,  g_hh1);
    cudaGetSymbolAddress((void**)&p_as1,  g_as1);
    cudaGetSymbolAddress((void**)&p_ad1,  g_ad1);
    cudaGetSymbolAddress((void**)&p_h2,   g_h2);
    cudaGetSymbolAddress((void**)&p_as2,  g_as2);
    cudaGetSymbolAddress((void**)&p_ad2,  g_ad2);
    cudaGetSymbolAddress((void**)&p_imp,  g_imp);

    int egrid  = (E + 255) / 256;
    int g1grid = (N + 63) / 64;
    int NB     = (N + 1023) / 1024;   // <= 98

    // K0: csr_count || gemm1(+pack). g_deg is zero on entry (zero-init at
    // load; re-zeroed by csr_scatter at the end of every call).
    count_gemm1_kernel<<<egrid + g1grid, 256>>>(ei, E, egrid, x, W1, as1w,
                                                ad1w, p_hh1, p_as1, p_ad1, N);
    scanA_kernel<<<NB, 1024>>>(N);
    scanC_kernel<<<NB, 1024>>>(N);
    csr_scatter_kernel<<<egrid, 256>>>(ei, E, N);

    // layer-1 aggregation fused with layer-2 GEMM + coefs (profiled slot)
    gat_agg1_fused_kernel<<<(N + 7) / 8, 256>>>(p_as1, p_ad1, p_hh1, b1,
                                                W2, as2w, ad2w,
                                                p_h2, p_as2, p_ad2, N);

    float* embeds_dst = (out_size >= N * 32) ? out : p_h2;
    float* imp_dst    = (out_size >= N * 33) ? (out + (size_t)N * 32) : nullptr;
    float* idx_dst    = (out_size >= N * 33 + 5) ? (out + (size_t)N * 33) : nullptr;

    // layer-2 aggregation
    gat_agg2_kernel<<<(N + 7) / 8, 256>>>(p_as2, p_ad2, p_h2, b2,
                                          embeds_dst, p_imp, imp_dst, N);

    // top-k (two-stage)
    topk_stage1_kernel<<<TK_BLOCKS, 256>>>(p_imp, N);
    topk_stage2_kernel<<<1, 256>>>(idx_dst);
}

// round 13
// speedup vs baseline: 1.1201x; 1.0023x over previous
#include <cuda_runtime.h>
#include <cuda_fp16.h>
#include <math.h>

#define NN 100000
#define EE 3400000
#define NEG_SLOPE 0.2f

// ---------------- scratch (device globals; no allocations allowed) ----------
__device__ __half2 g_hh1[NN * 32];     // layer1 features packed (head0,head1)
__device__ float   g_as1[NN * 2];
__device__ float   g_ad1[NN * 2];
__device__ float   g_h2[NN * 32];
__device__ float   g_as2[NN];
__device__ float   g_ad2[NN];
__device__ float   g_imp[NN];

// CSR by destination (shared by both layers)
__device__ int g_deg[NN];              // zero-init at load; re-zeroed by scatter
__device__ int g_rowstart[NN + 1];
__device__ int g_cursor[NN];
__device__ int g_col[EE];
__device__ int g_bsum[128];            // scan phase-A partials

// top-k staging
#define TK_BLOCKS 128
__device__ float g_cand_v[TK_BLOCKS * 5];
__device__ int   g_cand_i[TK_BLOCKS * 5];

__device__ __forceinline__ float lrelu(float x) {
    return x > 0.f ? x : NEG_SLOPE * x;
}

// Inline edge-index dtype detection: int64 (values < 2^31) => all odd 32-bit
// words of the first 32 elements are zero. Warp-uniform, deterministic.
__device__ __forceinline__ int detect_idx64_warp(const int* ei32) {
    int lane = threadIdx.x & 31;
    int v = ei32[2 * lane + 1];
    unsigned nz = __ballot_sync(0xFFFFFFFFu, v != 0);
    return nz == 0 ? 1 : 0;
}

__device__ __forceinline__ int warp_incl_scan(int v, int lane) {
    #pragma unroll
    for (int o = 1; o < 32; o <<= 1) {
        int n = __shfl_up_sync(0xFFFFFFFFu, v, o);
        if (lane >= o) v += n;
    }
    return v;
}

// ------------------- K0: fat kernel = csr_count || gemm1 --------------------
__global__ void count_gemm1_kernel(const void* __restrict__ ei, int E,
                                   int egrid,
                                   const float* __restrict__ x,
                                   const float* __restrict__ W,
                                   const float* __restrict__ att_src,
                                   const float* __restrict__ att_dst,
                                   __half2* __restrict__ hh,
                                   float* __restrict__ asrc,
                                   float* __restrict__ adst,
                                   int N) {
    constexpr int IN = 64, COLS = 64, RPI = 4, ITERS = 16;
    __shared__ float Ws[IN * COLS];
    __shared__ float as_s[COLS];
    __shared__ float ad_s[COLS];
    __shared__ float xs[RPI][IN];
    __shared__ float hs[RPI][COLS];

    int t = threadIdx.x;

    if (blockIdx.x < egrid) {
        int idx64 = detect_idx64_warp((const int*)ei);
        int i = blockIdx.x * 256 + t;
        if (i >= E) return;
        int d;
        if (idx64) d = (int)((const long long*)ei)[E + i];
        else       d = ((const int*)ei)[E + i];
        atomicAdd(&g_deg[d], 1);
        return;
    }

    int gb = blockIdx.x - egrid;
    for (int i = t; i < IN * COLS; i += 256) Ws[i] = W[i];
    if (t < COLS) { as_s[t] = att_src[t]; ad_s[t] = att_dst[t]; }
    __syncthreads();

    int col  = t % COLS;
    int r    = t / COLS;
    int lane = t & 31;
    int head = col >> 5;
    long long row0 = (long long)gb * (RPI * ITERS);

    for (int it = 0; it < ITERS; ++it) {
        long long rowbase = row0 + (long long)it * RPI;
        __syncthreads();
        for (int i = t; i < RPI * IN; i += 256) {
            int rr = i / IN, k = i % IN;
            long long row = rowbase + rr;
            xs[rr][k] = (row < N) ? x[row * IN + k] : 0.f;
        }
        __syncthreads();

        long long row = rowbase + r;
        float acc = 0.f;
        #pragma unroll
        for (int k = 0; k < IN; ++k) acc += xs[r][k] * Ws[k * COLS + col];

        float s1 = acc * as_s[col];
        float s2 = acc * ad_s[col];
        #pragma unroll
        for (int o = 16; o > 0; o >>= 1) {
            s1 += __shfl_xor_sync(0xFFFFFFFFu, s1, o);
            s2 += __shfl_xor_sync(0xFFFFFFFFu, s2, o);
        }
        hs[r][col] = acc;
        if (row < N && lane == 0) {
            asrc[row * 2 + head] = s1;
            adst[row * 2 + head] = s2;
        }
        __syncthreads();
        if (col < 32 && row < N)
            hh[row * 32 + col] = __floats2half2_rn(hs[r][col], hs[r][col + 32]);
    }
}

// --------------------- 2-phase parallel exclusive scan ----------------------
__global__ void scanA_kernel(int N) {
    int tid = threadIdx.x, lane = tid & 31, wid = tid >> 5;
    int i = blockIdx.x * 1024 + tid;
    int v = (i < N) ? g_deg[i] : 0;
    #pragma unroll
    for (int o = 16; o; o >>= 1) v += __shfl_xor_sync(0xFFFFFFFFu, v, o);
    __shared__ int ws[32];
    if (lane == 0) ws[wid] = v;
    __syncthreads();
    if (wid == 0) {
        int s = ws[lane];
        #pragma unroll
        for (int o = 16; o; o >>= 1) s += __shfl_xor_sync(0xFFFFFFFFu, s, o);
        if (lane == 0) g_bsum[blockIdx.x] = s;
    }
}

__global__ void scanC_kernel(int N) {
    int tid = threadIdx.x, lane = tid & 31, wid = tid >> 5;
    __shared__ int boff_s;
    __shared__ int ws[32];

    if (wid == 0) {
        int acc = 0;
        for (int b = lane; b < blockIdx.x; b += 32) acc += g_bsum[b];
        #pragma unroll
        for (int o = 16; o; o >>= 1) acc += __shfl_xor_sync(0xFFFFFFFFu, acc, o);
        if (lane == 0) boff_s = acc;
    }

    int i = blockIdx.x * 1024 + tid;
    int v = (i < N) ? g_deg[i] : 0;
    int incl = warp_incl_scan(v, lane);
    if (lane == 31) ws[wid] = incl;
    __syncthreads();
    if (wid == 0) {
        int s = ws[lane];
        s = warp_incl_scan(s, lane);
        ws[lane] = s;
    }
    __syncthreads();
    int base = (wid > 0) ? ws[wid - 1] : 0;
    int excl = boff_s + base + incl - v;
    if (i < N) {
        g_rowstart[i] = excl;
        g_cursor[i]   = excl;
        if (i == N - 1) g_rowstart[N] = excl + v;
    }
}

// --------------- CSR scatter (also re-zeroes g_deg for next call) -----------
__global__ void csr_scatter_kernel(const void* __restrict__ ei, int E, int N) {
    int idx64 = detect_idx64_warp((const int*)ei);
    int i = blockIdx.x * blockDim.x + threadIdx.x;
    if (i < N) g_deg[i] = 0;          // restore zero-invariant for next launch
    if (i >= E) return;
    int s, d;
    if (idx64) {
        const long long* p = (const long long*)ei;
        s = (int)p[i]; d = (int)p[E + i];
    } else {
        const int* p = (const int*)ei;
        s = p[i]; d = p[E + i];
    }
    int pos = atomicAdd(&g_cursor[d], 1);
    g_col[pos] = s;
}

// ----- layer-1 aggregation FUSED with layer-2 GEMM + attention coefs --------
// warp per dst node; lane = feature dim. After computing hin2 row, multiply
// by W2 (shared) in-place and emit h2 row + as2/ad2 scalars.
__global__ void gat_agg1_fused_kernel(const float* __restrict__ asrc,
                                      const float* __restrict__ adst,
                                      const __half2* __restrict__ hh,
                                      const float* __restrict__ b1,
                                      const float* __restrict__ W2,
                                      const float* __restrict__ as2w,
                                      const float* __restrict__ ad2w,
                                      float* __restrict__ h2out,
                                      float* __restrict__ as2,
                                      float* __restrict__ ad2,
                                      int N) {
    __shared__ int   s_idx[8][32];
    __shared__ float s_w[8][2][32];
    __shared__ float W2s[32 * 32];
    __shared__ float a2s_s[32], a2d_s[32];

    int t = threadIdx.x;
    for (int i = t; i < 1024; i += 256) W2s[i] = W2[i];
    if (t < 32) { a2s_s[t] = as2w[t]; a2d_s[t] = ad2w[t]; }
    __syncthreads();

    int warp_id = (blockIdx.x * blockDim.x + t) >> 5;
    int lane  = t & 31;
    int wslot = (t >> 5) & 7;
    if (warp_id >= N) return;
    int d = warp_id;

    float ad0 = adst[d * 2 + 0];
    float ad1 = adst[d * 2 + 1];
    float w_self0 = __expf(lrelu(asrc[d * 2 + 0] + ad0));
    float w_self1 = __expf(lrelu(asrc[d * 2 + 1] + ad1));
    float2 hself = __half22float2(hh[d * 32 + lane]);
    float den0 = (lane == 0) ? w_self0 : 0.f;
    float den1 = (lane == 0) ? w_self1 : 0.f;
    float acc0 = w_self0 * hself.x;
    float acc1 = w_self1 * hself.y;

    int beg = g_rowstart[d], end = g_rowstart[d + 1];
    for (int base = beg; base < end; base += 32) {
        int j = base + lane;
        bool valid = j < end;
        int s = valid ? g_col[j] : 0;
        s_idx[wslot][lane] = s;

        float2 a2 = valid ? ((const float2*)asrc)[s] : make_float2(0.f, 0.f);
        float w0 = valid ? __expf(lrelu(a2.x + ad0)) : 0.f;
        float w1 = valid ? __expf(lrelu(a2.y + ad1)) : 0.f;
        den0 += w0; den1 += w1;
        s_w[wslot][0][lane] = w0;
        s_w[wslot][1][lane] = w1;
        __syncwarp();

        int cnt = end - base; if (cnt > 32) cnt = 32;
        if (cnt == 32) {
            #pragma unroll 8
            for (int k = 0; k < 32; ++k) {
                int sk = s_idx[wslot][k];
                float2 f = __half22float2(hh[sk * 32 + lane]);
                acc0 += s_w[wslot][0][k] * f.x;
                acc1 += s_w[wslot][1][k] * f.y;
            }
        } else {
            for (int k = 0; k < cnt; ++k) {
                int sk = s_idx[wslot][k];
                float2 f = __half22float2(hh[sk * 32 + lane]);
                acc0 += s_w[wslot][0][k] * f.x;
                acc1 += s_w[wslot][1][k] * f.y;
            }
        }
        __syncwarp();
    }

    #pragma unroll
    for (int o = 16; o; o >>= 1) {
        den0 += __shfl_xor_sync(0xFFFFFFFFu, den0, o);
        den1 += __shfl_xor_sync(0xFFFFFFFFu, den1, o);
    }
    float v = 0.5f * (acc0 / (den0 + 1e-16f) + acc1 / (den1 + 1e-16f)) + b1[lane];
    v = fmaxf(v, 0.f);                 // hin2 value for (d, lane)

    // ---- fused layer-2 GEMM (32x32) + attention coefficients ----
    s_w[wslot][0][lane] = v;
    __syncwarp();
    float h2v = 0.f;
    #pragma unroll
    for (int k = 0; k < 32; ++k)
        h2v += s_w[wslot][0][k] * W2s[k * 32 + lane];
    h2out[d * 32 + lane] = h2v;
    float c1 = h2v * a2s_s[lane];
    float c2 = h2v * a2d_s[lane];
    #pragma unroll
    for (int o = 16; o; o >>= 1) {
        c1 += __shfl_xor_sync(0xFFFFFFFFu, c1, o);
        c2 += __shfl_xor_sync(0xFFFFFFFFu, c2, o);
    }
    if (lane == 0) { as2[d] = c1; ad2[d] = c2; }
}

// --------- layer-2 softmax aggregation: warp per dst, fp32 features ---------
__global__ void gat_agg2_kernel(const float* __restrict__ asrc,
                                const float* __restrict__ adst,
                                const float* __restrict__ hfeat,
                                const float* __restrict__ bias,
                                float* __restrict__ outv,
                                float* __restrict__ imp_a,
                                float* __restrict__ imp_b,   // may be null
                                int N) {
    __shared__ int   s_idx[8][32];
    __shared__ float s_w[8][32];

    int warp_id = (blockIdx.x * blockDim.x + threadIdx.x) >> 5;
    int lane  = threadIdx.x & 31;
    int wslot = (threadIdx.x >> 5) & 7;
    if (warp_id >= N) return;
    int d = warp_id;

    float ad0 = adst[d];
    float w_self = __expf(lrelu(asrc[d] + ad0));
    float den = (lane == 0) ? w_self : 0.f;
    float acc = w_self * hfeat[d * 32 + lane];

    int beg = g_rowstart[d], end = g_rowstart[d + 1];
    for (int base = beg; base < end; base += 32) {
        int j = base + lane;
        bool valid = j < end;
        int s = valid ? g_col[j] : 0;
        s_idx[wslot][lane] = s;

        float w = valid ? __expf(lrelu(asrc[s] + ad0)) : 0.f;
        den += w;
        s_w[wslot][lane] = w;
        __syncwarp();

        int cnt = end - base; if (cnt > 32) cnt = 32;
        if (cnt == 32) {
            #pragma unroll 8
            for (int k = 0; k < 32; ++k) {
                int sk = s_idx[wslot][k];
                acc += s_w[wslot][k] * hfeat[sk * 32 + lane];
            }
        } else {
            for (int k = 0; k < cnt; ++k) {
                int sk = s_idx[wslot][k];
                acc += s_w[wslot][k] * hfeat[sk * 32 + lane];
            }
        }
        __syncwarp();
    }

    #pragma unroll
    for (int o = 16; o; o >>= 1)
        den += __shfl_xor_sync(0xFFFFFFFFu, den, o);
    float v = acc / (den + 1e-16f) + bias[lane];
    outv[d * 32 + lane] = v;
    float ss = v * v;
    #pragma unroll
    for (int o = 16; o; o >>= 1)
        ss += __shfl_xor_sync(0xFFFFFFFFu, ss, o);
    if (lane == 0) {
        float nm = sqrtf(ss);
        imp_a[d] = nm;
        if (imp_b) imp_b[d] = nm;
    }
}

// --------------------------------- top-k ------------------------------------
__global__ void topk_stage1_kernel(const float* __restrict__ imp, int N) {
    __shared__ float bv[256];
    __shared__ int   bi[256];
    __shared__ int   chosen[5];
    int chunk = (N + TK_BLOCKS - 1) / TK_BLOCKS;
    int lo = blockIdx.x * chunk;
    int hi = lo + chunk; if (hi > N) hi = N;
    for (int r = 0; r < 5; ++r) {
        float best = -1e30f; int besti = 0x7FFFFFFF;
        for (int i = lo + threadIdx.x; i < hi; i += 256) {
            bool skip = false;
            for (int c = 0; c < r; ++c) if (chosen[c] == i) skip = true;
            if (skip) continue;
            float v = imp[i];
            if (v > best || (v == best && i < besti)) { best = v; besti = i; }
        }
        bv[threadIdx.x] = best;
        bi[threadIdx.x] = besti;
        __syncthreads();
        if (threadIdx.x == 0) {
            float B = -1e30f; int BI = 0x7FFFFFFF;
            for (int t = 0; t < 256; ++t)
                if (bv[t] > B || (bv[t] == B && bi[t] < BI)) { B = bv[t]; BI = bi[t]; }
            chosen[r] = BI;
            g_cand_v[blockIdx.x * 5 + r] = B;
            g_cand_i[blockIdx.x * 5 + r] = BI;
        }
        __syncthreads();
    }
}

__global__ void topk_stage2_kernel(float* __restrict__ out_idx) {
    __shared__ float bv[256];
    __shared__ int   bi[256];
    __shared__ int   chosen[5];
    const int M = TK_BLOCKS * 5;
    for (int r = 0; r < 5; ++r) {
        float best = -1e30f; int besti = 0x7FFFFFFF;
        for (int i = threadIdx.x; i < M; i += 256) {
            int gi = g_cand_i[i];
            bool skip = false;
            for (int c = 0; c < r; ++c) if (chosen[c] == gi) skip = true;
            if (skip) continue;
            float v = g_cand_v[i];
            if (v > best || (v == best && gi < besti)) { best = v; besti = gi; }
        }
        bv[threadIdx.x] = best;
        bi[threadIdx.x] = besti;
        __syncthreads();
        if (threadIdx.x == 0) {
            float B = -1e30f; int BI = 0x7FFFFFFF;
            for (int t = 0; t < 256; ++t)
                if (bv[t] > B || (bv[t] == B && bi[t] < BI)) { B = bv[t]; BI = bi[t]; }
            chosen[r] = BI;
            if (out_idx) out_idx[r] = (float)BI;
        }
        __syncthreads();
    }
}

// --------------------------------- launch -----------------------------------
extern "C" void kernel_launch(void* const* d_in, const int* in_sizes, int n_in,
                              void* d_out, int out_size) {
    const float* x    = (const float*)d_in[0];
    const void*  ei   = d_in[1];
    const float* W1   = (const float*)d_in[2];
    const float* as1w = (const float*)d_in[3];
    const float* ad1w = (const float*)d_in[4];
    const float* b1   = (const float*)d_in[5];
    const float* W2   = (const float*)d_in[6];
    const float* as2w = (const float*)d_in[7];
    const float* ad2w = (const float*)d_in[8];
    const float* b2   = (const float*)d_in[9];
    float* out = (float*)d_out;

    int N = in_sizes[0] / 64;
    int E = in_sizes[1] / 2;
    if (N > NN) N = NN;
    if (E > EE) E = EE;

    float *p_as1, *p_ad1, *p_h2, *p_as2, *p_ad2, *p_imp;
    __half2 *p_hh1;
    cudaGetSymbolAddress((void**)&p_hh1,  g_hh1);
    cudaGetSymbolAddress((void**)&p_as1,  g_as1);
    cudaGetSymbolAddress((void**)&p_ad1,  g_ad1);
    cudaGetSymbolAddress((void**)&p_h2,   g_h2);
    cudaGetSymbolAddress((void**)&p_as2,  g_as2);
    cudaGetSymbolAddress((void**)&p_ad2,  g_ad2);
    cudaGetSymbolAddress((void**)&p_imp,  g_imp);

    int egrid  = (E + 255) / 256;
    int g1grid = (N + 63) / 64;
    int NB     = (N + 1023) / 1024;   // <= 98

    // K0: csr_count || gemm1(+pack). g_deg is zero on entry (zero-init at
    // load; re-zeroed by csr_scatter at the end of every call).
    count_gemm1_kernel<<<egrid + g1grid, 256>>>(ei, E, egrid, x, W1, as1w,
                                                ad1w, p_hh1, p_as1, p_ad1, N);
    scanA_kernel<<<NB, 1024>>>(N);
    scanC_kernel<<<NB, 1024>>>(N);
    csr_scatter_kernel<<<egrid, 256>>>(ei, E, N);

    // layer-1 aggregation fused with layer-2 GEMM + coefs (profiled slot)
    gat_agg1_fused_kernel<<<(N + 7) / 8, 256>>>(p_as1, p_ad1, p_hh1, b1,
                                                W2, as2w, ad2w,
                                                p_h2, p_as2, p_ad2, N);

    float* embeds_dst = (out_size >= N * 32) ? out : p_h2;
    float* imp_dst    = (out_size >= N * 33) ? (out + (size_t)N * 32) : nullptr;
    float* idx_dst    = (out_size >= N * 33 + 5) ? (out + (size_t)N * 33) : nullptr;

    // layer-2 aggregation
    gat_agg2_kernel<<<(N + 7) / 8, 256>>>(p_as2, p_ad2, p_h2, b2,
                                          embeds_dst, p_imp, imp_dst, N);

    // top-k (two-stage)
    topk_stage1_kernel<<<TK_BLOCKS, 256>>>(p_imp, N);
    topk_stage2_kernel<<<1, 256>>>(idx_dst);
}